// round 3
// baseline (speedup 1.0000x reference)
#include <cuda_runtime.h>

// LSTM(B=8192, T=1024, H=10, in=1) -> final cell state -> Linear(10,1).
// Layout: 5 lanes per batch element ("group"), lane r owns hidden units 2r, 2r+1.
// 6 groups per warp (lanes 0..29 active, 30/31 idle-but-converged).
// All recurrent weights live in registers as f32x2 pairs; gate math uses
// fma.rn.f32x2 (Blackwell packed fp32 FMA) -> half the FMA-pipe issues.
// h broadcast within a group via unrolled __shfl_sync. c,h never leave registers.

#define B_TOT 8192
#define T_LEN 1024
#define HID   10

#define LPG 5   // lanes per group (batch element)
#define GPW 6   // groups per warp
#define WARPS_PER_BLOCK 4
#define THREADS_PER_BLOCK (WARPS_PER_BLOCK * 32)
#define BATCH_PER_BLOCK (WARPS_PER_BLOCK * GPW)   // 24

// ---------- f32x2 helpers ----------
__device__ __forceinline__ unsigned long long pack2(float x, float y) {
    unsigned long long r;
    asm("mov.b64 %0, {%1, %2};" : "=l"(r) : "f"(x), "f"(y));
    return r;
}
__device__ __forceinline__ void unpack2(unsigned long long v, float& x, float& y) {
    asm("mov.b64 {%0, %1}, %2;" : "=f"(x), "=f"(y) : "l"(v));
}
__device__ __forceinline__ unsigned long long ffma2(unsigned long long a,
                                                    unsigned long long b,
                                                    unsigned long long c) {
    unsigned long long d;
    asm("fma.rn.f32x2 %0, %1, %2, %3;" : "=l"(d) : "l"(a), "l"(b), "l"(c));
    return d;
}

// ---------- activations (accurate: ex2/rcp approx have ~2^-22 rel err) ----------
__device__ __forceinline__ float fsigmoid(float x) {
    float e, r;
    // exp(-x) = 2^(-x * log2(e))
    asm("ex2.approx.f32 %0, %1;" : "=f"(e) : "f"(x * -1.4426950408889634f));
    asm("rcp.approx.f32 %0, %1;" : "=f"(r) : "f"(e + 1.0f));
    return r;
}
__device__ __forceinline__ float ftanh_acc(float x) {
    // tanh(x) = 2*sigmoid(2x) - 1
    return fmaf(2.0f, fsigmoid(2.0f * x), -1.0f);
}

__global__ __launch_bounds__(THREADS_PER_BLOCK, 3)
void lstm_lin_kernel(const float* __restrict__ x,       // [B, T, 1]
                     const float* __restrict__ W_ih,    // [4H, 1]
                     const float* __restrict__ W_hh,    // [4H, H]
                     const float* __restrict__ b_ih,    // [4H]
                     const float* __restrict__ b_hh,    // [4H]
                     const float* __restrict__ W_lin,   // [1, H]
                     const float* __restrict__ b_lin,   // [1]
                     float* __restrict__ out)           // [B, 1]
{
    const int warp  = threadIdx.x >> 5;
    const int wlane = threadIdx.x & 31;
    const int group = wlane / LPG;              // 0..5 active, 6 => idle lanes 30/31
    const int r     = wlane % LPG;              // 0..4
    const int base  = group * LPG;              // group base lane within warp
    const bool active = (group < GPW);

    const int gbatch = (blockIdx.x * WARPS_PER_BLOCK + warp) * GPW + group;
    const bool valid = active && (gbatch < B_TOT);
    const int b = valid ? gbatch : 0;           // clamp so idle lanes load safely

    const int u0 = 2 * r;                        // this lane's hidden units: u0, u0+1

    // ---- load per-lane weights into registers (once; loop runs 1024 steps) ----
    unsigned long long w2[4][HID];   // w2[gate][k] = (W_hh[gate*10+u0][k], W_hh[gate*10+u0+1][k])
    unsigned long long wih2[4];      // (W_ih[gate*10+u0], W_ih[gate*10+u0+1])
    unsigned long long bias2[4];     // combined bias, same pairing
#pragma unroll
    for (int g = 0; g < 4; g++) {
        const int row0 = g * HID + u0;
        const int row1 = row0 + 1;
#pragma unroll
        for (int k = 0; k < HID; k++)
            w2[g][k] = pack2(W_hh[row0 * HID + k], W_hh[row1 * HID + k]);
        wih2[g]  = pack2(W_ih[row0], W_ih[row1]);
        bias2[g] = pack2(b_ih[row0] + b_hh[row0], b_ih[row1] + b_hh[row1]);
    }

    float h0 = 0.0f, h1 = 0.0f;   // h[u0], h[u0+1]
    float c0 = 0.0f, c1 = 0.0f;   // c[u0], c[u0+1]

    const float4* __restrict__ xrow =
        reinterpret_cast<const float4*>(x + (size_t)b * T_LEN);

    for (int t4 = 0; t4 < T_LEN / 4; t4++) {
        const float4 xq = __ldg(&xrow[t4]);
        float xs0 = xq.x, xs1 = xq.y, xs2 = xq.z, xs3 = xq.w;
        float xsel[4] = {xs0, xs1, xs2, xs3};

#pragma unroll
        for (int j = 0; j < 4; j++) {
            const float xt = xsel[j];
            const unsigned long long x2 = pack2(xt, xt);

            unsigned long long acc0 = ffma2(x2, wih2[0], bias2[0]);
            unsigned long long acc1 = ffma2(x2, wih2[1], bias2[1]);
            unsigned long long acc2 = ffma2(x2, wih2[2], bias2[2]);
            unsigned long long acc3 = ffma2(x2, wih2[3], bias2[3]);

            // recurrent matmul: broadcast h[k] from owning lane, 4 gates per k
#pragma unroll
            for (int k = 0; k < HID; k++) {
                const float hk = __shfl_sync(0xffffffffu,
                                             (k & 1) ? h1 : h0,
                                             base + (k >> 1));
                const unsigned long long hk2 = pack2(hk, hk);
                acc0 = ffma2(w2[0][k], hk2, acc0);
                acc1 = ffma2(w2[1][k], hk2, acc1);
                acc2 = ffma2(w2[2][k], hk2, acc2);
                acc3 = ffma2(w2[3][k], hk2, acc3);
            }

            float gi0, gi1, gf0, gf1, gg0, gg1, go0, go1;
            unpack2(acc0, gi0, gi1);
            unpack2(acc1, gf0, gf1);
            unpack2(acc2, gg0, gg1);
            unpack2(acc3, go0, go1);

            const float si0 = fsigmoid(gi0), si1 = fsigmoid(gi1);
            const float sf0 = fsigmoid(gf0), sf1 = fsigmoid(gf1);
            const float tg0 = ftanh_acc(gg0), tg1 = ftanh_acc(gg1);
            const float so0 = fsigmoid(go0), so1 = fsigmoid(go1);

            c0 = fmaf(sf0, c0, si0 * tg0);
            c1 = fmaf(sf1, c1, si1 * tg1);
            h0 = so0 * ftanh_acc(c0);
            h1 = so1 * ftanh_acc(c1);
        }
    }

    // ---- epilogue: out[b] = sum_u c[u] * W_lin[u] + b_lin ----
    float part = c0 * W_lin[u0] + c1 * W_lin[u0 + 1];
    const float p1 = __shfl_sync(0xffffffffu, part, base + 1);
    const float p2 = __shfl_sync(0xffffffffu, part, base + 2);
    const float p3 = __shfl_sync(0xffffffffu, part, base + 3);
    const float p4 = __shfl_sync(0xffffffffu, part, base + 4);

    if (valid && r == 0) {
        out[gbatch] = part + p1 + p2 + p3 + p4 + b_lin[0];
    }
}

extern "C" void kernel_launch(void* const* d_in, const int* in_sizes, int n_in,
                              void* d_out, int out_size) {
    const float* x     = (const float*)d_in[0];
    const float* W_ih  = (const float*)d_in[1];
    const float* W_hh  = (const float*)d_in[2];
    const float* b_ih  = (const float*)d_in[3];
    const float* b_hh  = (const float*)d_in[4];
    const float* W_lin = (const float*)d_in[5];
    const float* b_lin = (const float*)d_in[6];
    float* out = (float*)d_out;

    const int blocks = (B_TOT + BATCH_PER_BLOCK - 1) / BATCH_PER_BLOCK;  // 342
    lstm_lin_kernel<<<blocks, THREADS_PER_BLOCK>>>(
        x, W_ih, W_hh, b_ih, b_hh, W_lin, b_lin, out);
}

// round 4
// speedup vs baseline: 1.3497x; 1.3497x over previous
#include <cuda_runtime.h>

// LSTM(B=8192, T=1024, H=10, in=1) -> final cell state c_T -> Linear(10,1).
//
// Layout: 5 lanes per batch ("group"), lane r owns hidden units 2r, 2r+1.
// 6 groups per warp (lanes 0..29 active). All weights in registers.
//
// Key tricks this revision:
//  * tanh.approx.f32 (1 MUFU) for ALL activations. sigmoid folded as
//    sigma(x) = 0.5 + 0.5*tanh(x/2) with the 0.5 pre-scaled into W/b of the
//    i,f,o rows. Recurrent state carried as h' = 2h (the 0.5 folded into
//    W_hh), so h' = fma(tanh_o, tanh_c, tanh_c) -- no sigma_o needed.
//  * k-pair f32x2 accumulation: acc[gate][unit] = ((even-k sum),(odd-k sum)).
//    The h operand pair (h[2j], h[2j+1]) is exactly lane base+j's packed
//    state -> one 64-bit shuffle, zero pack MOVs.
//  * x folded in as a 6th k-pair (x, 1) against (W_ih, bias).
//  * c/h elementwise update packed as f32x2.

#define B_TOT 8192
#define T_LEN 1024
#define HID   10

#define LPG 5
#define GPW 6
#define WARPS_PER_BLOCK 4
#define THREADS_PER_BLOCK (WARPS_PER_BLOCK * 32)
#define BATCH_PER_BLOCK (WARPS_PER_BLOCK * GPW)   // 24

typedef unsigned long long ull;

// ---------- f32x2 helpers ----------
__device__ __forceinline__ ull pack2(float x, float y) {
    ull r;
    asm("mov.b64 %0, {%1, %2};" : "=l"(r) : "f"(x), "f"(y));
    return r;
}
__device__ __forceinline__ void unpack2(ull v, float& x, float& y) {
    asm("mov.b64 {%0, %1}, %2;" : "=f"(x), "=f"(y) : "l"(v));
}
__device__ __forceinline__ ull ffma2(ull a, ull b, ull c) {
    ull d;
    asm("fma.rn.f32x2 %0, %1, %2, %3;" : "=l"(d) : "l"(a), "l"(b), "l"(c));
    return d;
}
__device__ __forceinline__ ull fmul2(ull a, ull b) {
    ull d;
    asm("mul.rn.f32x2 %0, %1, %2;" : "=l"(d) : "l"(a), "l"(b));
    return d;
}
__device__ __forceinline__ float ftanh(float x) {
    float r;
    asm("tanh.approx.f32 %0, %1;" : "=f"(r) : "f"(x));
    return r;
}

__global__ __launch_bounds__(THREADS_PER_BLOCK, 3)
void lstm_lin_kernel(const float* __restrict__ x,       // [B, T, 1]
                     const float* __restrict__ W_ih,    // [4H, 1]
                     const float* __restrict__ W_hh,    // [4H, H]
                     const float* __restrict__ b_ih,    // [4H]
                     const float* __restrict__ b_hh,    // [4H]
                     const float* __restrict__ W_lin,   // [1, H]
                     const float* __restrict__ b_lin,   // [1]
                     float* __restrict__ out)           // [B, 1]
{
    const int warp  = threadIdx.x >> 5;
    const int wlane = threadIdx.x & 31;
    const int group = wlane / LPG;           // 0..5 active; 6 => lanes 30,31 idle
    const int r     = wlane % LPG;           // 0..4
    const int base  = group * LPG;
    const bool active = (group < GPW);

    const int gbatch = (blockIdx.x * WARPS_PER_BLOCK + warp) * GPW + group;
    const bool valid = active && (gbatch < B_TOT);
    const int b = valid ? gbatch : 0;        // clamp so idle lanes load safely

    const int u0 = 2 * r;                    // this lane's units: u0, u0+1

    // ---- per-lane weights in registers, k-paired & pre-scaled ----
    // ge = g*2 + e : gate g in {i,f,g,o}, unit offset e in {0,1}
    // sg = 0.5 for sigmoid gates (i,f,o), 1.0 for the tanh gate (g).
    // W_hh additionally x0.5 because the carried state is h' = 2h.
    ull w2[8][5];     // w2[ge][j] = sg*0.5*(W_hh[row][2j], W_hh[row][2j+1])
    ull wx2[8];       // (sg*W_ih[row], sg*(b_ih[row]+b_hh[row]))
#pragma unroll
    for (int g = 0; g < 4; g++) {
        const float sg = (g == 2) ? 1.0f : 0.5f;
#pragma unroll
        for (int e = 0; e < 2; e++) {
            const int row = g * HID + u0 + e;
            const int ge  = g * 2 + e;
#pragma unroll
            for (int j = 0; j < 5; j++)
                w2[ge][j] = pack2(W_hh[row * HID + 2 * j]     * sg * 0.5f,
                                  W_hh[row * HID + 2 * j + 1] * sg * 0.5f);
            wx2[ge] = pack2(W_ih[row] * sg,
                            (b_ih[row] + b_hh[row]) * sg);
        }
    }

    const ull H2 = pack2(0.5f, 0.5f);

    ull h2 = pack2(0.0f, 0.0f);   // (h'[u0], h'[u0+1]),  h' = 2h
    ull c2 = pack2(0.0f, 0.0f);   // (c[u0],  c[u0+1]),   true cell state

    const float4* __restrict__ xrow =
        reinterpret_cast<const float4*>(x + (size_t)b * T_LEN);

    for (int t4 = 0; t4 < T_LEN / 4; t4++) {
        const float4 xq = __ldg(&xrow[t4]);
        const float xsel[4] = {xq.x, xq.y, xq.z, xq.w};

#pragma unroll
        for (int jt = 0; jt < 4; jt++) {
            // broadcast packed h' pairs: lane base+j holds (h[2j], h[2j+1])
            ull hp[5];
#pragma unroll
            for (int j = 0; j < 5; j++)
                hp[j] = __shfl_sync(0xffffffffu, h2, base + j);

            const ull xp = pack2(xsel[jt], 1.0f);

            ull acc[8];
#pragma unroll
            for (int ge = 0; ge < 8; ge++)
                acc[ge] = fmul2(wx2[ge], xp);          // x*W_ih in .lo, bias in .hi
#pragma unroll
            for (int j = 0; j < 5; j++)
#pragma unroll
                for (int ge = 0; ge < 8; ge++)
                    acc[ge] = ffma2(w2[ge][j], hp[j], acc[ge]);

            // horizontal add + tanh
            float t[8];
#pragma unroll
            for (int ge = 0; ge < 8; ge++) {
                float lo, hi;
                unpack2(acc[ge], lo, hi);
                t[ge] = ftanh(lo + hi);
            }

            const ull ti2 = pack2(t[0], t[1]);
            const ull tf2 = pack2(t[2], t[3]);
            const ull tg2 = pack2(t[4], t[5]);
            const ull to2 = pack2(t[6], t[7]);

            // c = sigma_f*c + sigma_i*tanh_g   (sigma = 0.5 + 0.5*t)
            const ull sf2 = ffma2(H2, tf2, H2);
            const ull si2 = ffma2(H2, ti2, H2);
            const ull p2  = fmul2(si2, tg2);
            c2 = ffma2(sf2, c2, p2);

            // h' = 2h = (1 + tanh_o) * tanh(c)
            float c0, c1;
            unpack2(c2, c0, c1);
            const ull tc2 = pack2(ftanh(c0), ftanh(c1));
            h2 = ffma2(to2, tc2, tc2);
        }
    }

    // ---- epilogue: out[b] = sum_u c[u] * W_lin[u] + b_lin ----
    float c0, c1;
    unpack2(c2, c0, c1);
    float part = c0 * W_lin[u0] + c1 * W_lin[u0 + 1];
    const float p1 = __shfl_sync(0xffffffffu, part, base + 1);
    const float p2 = __shfl_sync(0xffffffffu, part, base + 2);
    const float p3 = __shfl_sync(0xffffffffu, part, base + 3);
    const float p4 = __shfl_sync(0xffffffffu, part, base + 4);

    if (valid && r == 0) {
        out[gbatch] = part + p1 + p2 + p3 + p4 + b_lin[0];
    }
}

extern "C" void kernel_launch(void* const* d_in, const int* in_sizes, int n_in,
                              void* d_out, int out_size) {
    const float* x     = (const float*)d_in[0];
    const float* W_ih  = (const float*)d_in[1];
    const float* W_hh  = (const float*)d_in[2];
    const float* b_ih  = (const float*)d_in[3];
    const float* b_hh  = (const float*)d_in[4];
    const float* W_lin = (const float*)d_in[5];
    const float* b_lin = (const float*)d_in[6];
    float* out = (float*)d_out;

    const int blocks = (B_TOT + BATCH_PER_BLOCK - 1) / BATCH_PER_BLOCK;  // 342
    lstm_lin_kernel<<<blocks, THREADS_PER_BLOCK>>>(
        x, W_ih, W_hh, b_ih, b_hh, W_lin, b_lin, out);
}

// round 5
// speedup vs baseline: 1.4705x; 1.0895x over previous
#include <cuda_runtime.h>

// LSTM(B=8192, T=1024, H=10, in=1) -> final cell state c_T -> Linear(10,1).
//
// Decomposition (this revision): 10 lanes per batch, ONE hidden unit per lane,
// 3 batches per warp (lanes 0..29; 30/31 idle-but-converged).
// -> 683 blocks x 4 warps = 2732 warps (~4.6/SMSP), double the previous
//    occupancy, to cover the per-step serial dependency chain.
//
// Math tricks kept from R3:
//  * tanh.approx.f32 for all activations; sigma(x)=0.5+0.5*tanh(x/2) folded
//    into pre-scaled weights; state carried as h' = 2h so
//    h' = fma(tanh_o, tanh_c, tanh_c) (no sigma_o).
//  * k-pair f32x2 dot products: acc[g] = ((even-k sum),(odd-k sum)),
//    h-pairs gathered with two scalar shuffles + one pack each.
//  * x folded in via (x, 1) against (W_ih, bias) pair.

#define B_TOT 8192
#define T_LEN 1024
#define HID   10

#define LPG 10                  // lanes per group (batch)
#define GPW 3                   // groups per warp
#define WARPS_PER_BLOCK 4
#define THREADS_PER_BLOCK (WARPS_PER_BLOCK * 32)
#define BATCH_PER_BLOCK (WARPS_PER_BLOCK * GPW)   // 12

typedef unsigned long long ull;

// ---------- f32x2 helpers ----------
__device__ __forceinline__ ull pack2(float x, float y) {
    ull r;
    asm("mov.b64 %0, {%1, %2};" : "=l"(r) : "f"(x), "f"(y));
    return r;
}
__device__ __forceinline__ void unpack2(ull v, float& x, float& y) {
    asm("mov.b64 {%0, %1}, %2;" : "=f"(x), "=f"(y) : "l"(v));
}
__device__ __forceinline__ ull ffma2(ull a, ull b, ull c) {
    ull d;
    asm("fma.rn.f32x2 %0, %1, %2, %3;" : "=l"(d) : "l"(a), "l"(b), "l"(c));
    return d;
}
__device__ __forceinline__ ull fmul2(ull a, ull b) {
    ull d;
    asm("mul.rn.f32x2 %0, %1, %2;" : "=l"(d) : "l"(a), "l"(b));
    return d;
}
__device__ __forceinline__ float ftanh(float x) {
    float r;
    asm("tanh.approx.f32 %0, %1;" : "=f"(r) : "f"(x));
    return r;
}

__global__ __launch_bounds__(THREADS_PER_BLOCK, 5)   // keep regs <= 102: all 683 blocks resident
void lstm_lin_kernel(const float* __restrict__ x,       // [B, T, 1]
                     const float* __restrict__ W_ih,    // [4H, 1]
                     const float* __restrict__ W_hh,    // [4H, H]
                     const float* __restrict__ b_ih,    // [4H]
                     const float* __restrict__ b_hh,    // [4H]
                     const float* __restrict__ W_lin,   // [1, H]
                     const float* __restrict__ b_lin,   // [1]
                     float* __restrict__ out)           // [B, 1]
{
    const int warp  = threadIdx.x >> 5;
    const int wlane = threadIdx.x & 31;
    const int group = wlane / LPG;           // 0..2 active; 3 => lanes 30,31 idle
    const int r     = wlane - group * LPG;   // unit index 0..9
    const int base  = group * LPG;           // even (0,10,20)
    const bool active = (group < GPW);

    const int gbatch = (blockIdx.x * WARPS_PER_BLOCK + warp) * GPW + group;
    const bool valid = active && (gbatch < B_TOT);
    const int b = valid ? gbatch : 0;        // clamp so idle lanes load safely

    // ---- per-lane weights in registers, k-paired & pre-scaled ----
    // gate g in {i,f,g,o}; sg = 0.5 for sigmoid gates, 1.0 for tanh gate.
    // Extra 0.5 on W_hh because carried state is h' = 2h.
    ull w2[4][5];   // w2[g][j] = sg*0.5*(W_hh[row][2j], W_hh[row][2j+1])
    ull wx2[4];     // (sg*W_ih[row], sg*(b_ih[row]+b_hh[row]))
#pragma unroll
    for (int g = 0; g < 4; g++) {
        const float sg = (g == 2) ? 1.0f : 0.5f;
        const int row = g * HID + r;
#pragma unroll
        for (int j = 0; j < 5; j++)
            w2[g][j] = pack2(W_hh[row * HID + 2 * j]     * sg * 0.5f,
                             W_hh[row * HID + 2 * j + 1] * sg * 0.5f);
        wx2[g] = pack2(W_ih[row] * sg, (b_ih[row] + b_hh[row]) * sg);
    }

    float hn = 0.0f;   // h'[r] = 2*h[r]
    float c  = 0.0f;   // true cell state c[r]

    const float4* __restrict__ xrow =
        reinterpret_cast<const float4*>(x + (size_t)b * T_LEN);

    for (int t4 = 0; t4 < T_LEN / 4; t4++) {
        const float4 xq = __ldg(&xrow[t4]);
        const float xsel[4] = {xq.x, xq.y, xq.z, xq.w};

#pragma unroll
        for (int jt = 0; jt < 4; jt++) {
            // gather packed h'-pairs (h'[2j], h'[2j+1]) from owning lanes
            ull hp[5];
#pragma unroll
            for (int j = 0; j < 5; j++) {
                const float lo = __shfl_sync(0xffffffffu, hn, base + 2 * j);
                const float hi = __shfl_sync(0xffffffffu, hn, base + 2 * j + 1);
                hp[j] = pack2(lo, hi);
            }

            const ull xp = pack2(xsel[jt], 1.0f);

            ull acc[4];
#pragma unroll
            for (int g = 0; g < 4; g++)
                acc[g] = fmul2(wx2[g], xp);     // x*W_ih in .lo, bias in .hi
#pragma unroll
            for (int j = 0; j < 5; j++)
#pragma unroll
                for (int g = 0; g < 4; g++)
                    acc[g] = ffma2(w2[g][j], hp[j], acc[g]);

            float t[4];
#pragma unroll
            for (int g = 0; g < 4; g++) {
                float lo, hi;
                unpack2(acc[g], lo, hi);
                t[g] = ftanh(lo + hi);
            }

            // c = sigma_f*c + sigma_i*tanh_g   (sigma = 0.5 + 0.5*t)
            const float sf = fmaf(0.5f, t[1], 0.5f);
            const float si = fmaf(0.5f, t[0], 0.5f);
            c = fmaf(sf, c, si * t[2]);

            // h' = 2h = (1 + tanh_o) * tanh(c)
            const float tc = ftanh(c);
            hn = fmaf(t[3], tc, tc);
        }
    }

    // ---- epilogue: out[b] = sum_u c[u] * W_lin[u] + b_lin ----
    float part = c * W_lin[r];
    float sum = part;
#pragma unroll
    for (int j = 1; j < LPG; j++)
        sum += __shfl_sync(0xffffffffu, part, base + j);

    if (valid && r == 0) {
        out[gbatch] = sum + b_lin[0];
    }
}

extern "C" void kernel_launch(void* const* d_in, const int* in_sizes, int n_in,
                              void* d_out, int out_size) {
    const float* x     = (const float*)d_in[0];
    const float* W_ih  = (const float*)d_in[1];
    const float* W_hh  = (const float*)d_in[2];
    const float* b_ih  = (const float*)d_in[3];
    const float* b_hh  = (const float*)d_in[4];
    const float* W_lin = (const float*)d_in[5];
    const float* b_lin = (const float*)d_in[6];
    float* out = (float*)d_out;

    const int blocks = (B_TOT + BATCH_PER_BLOCK - 1) / BATCH_PER_BLOCK;  // 683
    lstm_lin_kernel<<<blocks, THREADS_PER_BLOCK>>>(
        x, W_ih, W_hh, b_ih, b_hh, W_lin, b_lin, out);
}

// round 6
// speedup vs baseline: 1.5976x; 1.0865x over previous
#include <cuda_runtime.h>

// LSTM(B=8192, T=1024, H=10, in=1) -> final cell state c_T -> Linear(10,1).
//
// Decomposition: 10 lanes per batch ("group"), ONE hidden unit per lane,
// 3 groups per warp (lanes 0..29 active). 683 blocks x 4 warps.
//
// This revision: h exchange via DOUBLE-BUFFERED SMEM table instead of 10
// scalar shuffles. Each lane: 1 STS (its h' scalar) + 2 LDS.128 + 1 LDS.64
// (group h-vector, broadcast, conflict-free) + 1 __syncwarp per step.
// ulonglong2 loads give the f32x2 operand pairs in aligned register pairs
// directly -> zero pack MOVs. MIO traffic per step drops 10 -> 4 ops.
//
// Math (kept): tanh.approx for all activations; sigma(x)=0.5+0.5*tanh(x/2)
// folded into pre-scaled weights; state carried as h' = 2h so
// h' = fma(tanh_o, tanh_c, tanh_c); x folded via (x,1) vs (W_ih, bias).

#define B_TOT 8192
#define T_LEN 1024
#define HID   10

#define LPG 10
#define GPW 3
#define WARPS_PER_BLOCK 4
#define THREADS_PER_BLOCK (WARPS_PER_BLOCK * 32)
#define BATCH_PER_BLOCK (WARPS_PER_BLOCK * GPW)   // 12

typedef unsigned long long ull;

__device__ __forceinline__ ull pack2(float x, float y) {
    ull r;
    asm("mov.b64 %0, {%1, %2};" : "=l"(r) : "f"(x), "f"(y));
    return r;
}
__device__ __forceinline__ void unpack2(ull v, float& x, float& y) {
    asm("mov.b64 {%0, %1}, %2;" : "=f"(x), "=f"(y) : "l"(v));
}
__device__ __forceinline__ ull ffma2(ull a, ull b, ull c) {
    ull d;
    asm("fma.rn.f32x2 %0, %1, %2, %3;" : "=l"(d) : "l"(a), "l"(b), "l"(c));
    return d;
}
__device__ __forceinline__ ull fmul2(ull a, ull b) {
    ull d;
    asm("mul.rn.f32x2 %0, %1, %2;" : "=l"(d) : "l"(a), "l"(b));
    return d;
}
__device__ __forceinline__ float ftanh(float x) {
    float r;
    asm("tanh.approx.f32 %0, %1;" : "=f"(r) : "f"(x));
    return r;
}

__global__ __launch_bounds__(THREADS_PER_BLOCK, 5)
void lstm_lin_kernel(const float* __restrict__ x,       // [B, T, 1]
                     const float* __restrict__ W_ih,    // [4H, 1]
                     const float* __restrict__ W_hh,    // [4H, H]
                     const float* __restrict__ b_ih,    // [4H]
                     const float* __restrict__ b_hh,    // [4H]
                     const float* __restrict__ W_lin,   // [1, H]
                     const float* __restrict__ b_lin,   // [1]
                     float* __restrict__ out)           // [B, 1]
{
    // h table: [parity][warp][group][12 floats] ; 12-float (48B) stride keeps
    // group regions 16B-aligned, STS conflicts <= 2-way, LDS group-broadcast.
    __shared__ float hbuf[2][WARPS_PER_BLOCK][GPW][12];

    const int warp  = threadIdx.x >> 5;
    const int wlane = threadIdx.x & 31;
    const int group = wlane / LPG;           // 0..2 active; 3 => lanes 30,31 idle
    const int r     = wlane - group * LPG;   // unit index 0..9
    const int base  = group * LPG;
    const bool active = (group < GPW);
    const int sgrp   = active ? group : 0;   // clamp for safe smem addressing

    const int gbatch = (blockIdx.x * WARPS_PER_BLOCK + warp) * GPW + group;
    const bool valid = active && (gbatch < B_TOT);
    const int b = valid ? gbatch : 0;

    // ---- per-lane weights in registers, k-paired & pre-scaled ----
    ull w2[4][5];   // w2[g][j] = sg*0.5*(W_hh[row][2j], W_hh[row][2j+1])
    ull wx2[4];     // (sg*W_ih[row], sg*(b_ih[row]+b_hh[row]))
#pragma unroll
    for (int g = 0; g < 4; g++) {
        const float sg = (g == 2) ? 1.0f : 0.5f;
        const int row = g * HID + r;
#pragma unroll
        for (int j = 0; j < 5; j++)
            w2[g][j] = pack2(W_hh[row * HID + 2 * j]     * sg * 0.5f,
                             W_hh[row * HID + 2 * j + 1] * sg * 0.5f);
        wx2[g] = pack2(W_ih[row] * sg, (b_ih[row] + b_hh[row]) * sg);
    }

    float c = 0.0f;   // true cell state c[r]

    // init h' = 0 in parity-0 buffer
    hbuf[0][warp][sgrp][active ? r : 10] = 0.0f;
    __syncwarp();

    const float4* __restrict__ xrow =
        reinterpret_cast<const float4*>(x + (size_t)b * T_LEN);

    float* const myslot0 = &hbuf[0][warp][sgrp][active ? r : 10];
    float* const myslot1 = &hbuf[1][warp][sgrp][active ? r : 10];
    const ull* const grp0 = reinterpret_cast<const ull*>(&hbuf[0][warp][sgrp][0]);
    const ull* const grp1 = reinterpret_cast<const ull*>(&hbuf[1][warp][sgrp][0]);

    for (int t4 = 0; t4 < T_LEN / 4; t4++) {
        const float4 xq = __ldg(&xrow[t4]);
        const float xsel[4] = {xq.x, xq.y, xq.z, xq.w};

#pragma unroll
        for (int jt = 0; jt < 4; jt++) {
            // static parity: global step = t4*4 + jt, parity = jt & 1
            const ull* grd = (jt & 1) ? grp1 : grp0;   // read buffer
            float* wrs     = (jt & 1) ? myslot0 : myslot1;  // write buffer

            // group h'-pairs: 2x LDS.128 + 1x LDS.64, pairs land reg-aligned
            ull hp[5];
            {
                const ulonglong2 a = *reinterpret_cast<const ulonglong2*>(grd);
                const ulonglong2 bq = *reinterpret_cast<const ulonglong2*>(grd + 2);
                hp[0] = a.x;  hp[1] = a.y;
                hp[2] = bq.x; hp[3] = bq.y;
                hp[4] = grd[4];
            }

            const ull xp = pack2(xsel[jt], 1.0f);

            ull acc[4];
#pragma unroll
            for (int g = 0; g < 4; g++)
                acc[g] = fmul2(wx2[g], xp);     // x*W_ih in .lo, bias in .hi
#pragma unroll
            for (int j = 0; j < 5; j++)
#pragma unroll
                for (int g = 0; g < 4; g++)
                    acc[g] = ffma2(w2[g][j], hp[j], acc[g]);

            float t[4];
#pragma unroll
            for (int g = 0; g < 4; g++) {
                float lo, hi;
                unpack2(acc[g], lo, hi);
                t[g] = ftanh(lo + hi);
            }

            // c = sigma_f*c + sigma_i*tanh_g   (sigma = 0.5 + 0.5*t)
            const float sf = fmaf(0.5f, t[1], 0.5f);
            const float si = fmaf(0.5f, t[0], 0.5f);
            c = fmaf(sf, c, si * t[2]);

            // h' = 2h = (1 + tanh_o) * tanh(c)
            const float tc = ftanh(c);
            *wrs = fmaf(t[3], tc, tc);

            __syncwarp();
        }
    }

    // ---- epilogue: out[b] = sum_u c[u] * W_lin[u] + b_lin ----
    float part = c * W_lin[r < HID ? r : 0];
    float sum = part;
#pragma unroll
    for (int j = 1; j < LPG; j++)
        sum += __shfl_sync(0xffffffffu, part, base + j);

    if (valid && r == 0) {
        out[gbatch] = sum + b_lin[0];
    }
}

extern "C" void kernel_launch(void* const* d_in, const int* in_sizes, int n_in,
                              void* d_out, int out_size) {
    const float* x     = (const float*)d_in[0];
    const float* W_ih  = (const float*)d_in[1];
    const float* W_hh  = (const float*)d_in[2];
    const float* b_ih  = (const float*)d_in[3];
    const float* b_hh  = (const float*)d_in[4];
    const float* W_lin = (const float*)d_in[5];
    const float* b_lin = (const float*)d_in[6];
    float* out = (float*)d_out;

    const int blocks = (B_TOT + BATCH_PER_BLOCK - 1) / BATCH_PER_BLOCK;  // 683
    lstm_lin_kernel<<<blocks, THREADS_PER_BLOCK>>>(
        x, W_ih, W_hh, b_ih, b_hh, W_lin, b_lin, out);
}